// round 1
// baseline (speedup 1.0000x reference)
#include <cuda_runtime.h>
#include <math.h>

#define CC    10
#define NN    1152
#define DIN   8
#define DOUT  16
#define BB    256
#define BT    2        // batch elements per CTA
#define NPAD  17       // priors row stride (odd -> conflict-free strided access)
#define THREADS 256

// Shared memory layout (floats):
//   pri   : [BT][NN*NPAD]   = 39168
//   logit : [BT][NN]        =  2304
//   prb   : [BT][NN]        =  2304
//   red   : [BT][16][8]     =   256
//   outv  : [BT][16]        =    32
//   redw  : [16]            =    16
//   mxse  : [4]             =     4
#define SM_PRI   0
#define SM_LOG   (BT*NN*NPAD)
#define SM_PRB   (SM_LOG + BT*NN)
#define SM_RED   (SM_PRB + BT*NN)
#define SM_OUTV  (SM_RED + BT*16*8)
#define SM_REDW  (SM_OUTV + BT*16)
#define SM_MXSE  (SM_REDW + 16)
#define SM_FLOATS (SM_MXSE + 4)

__global__ __launch_bounds__(THREADS, 1)
void caps_routing_kernel(const float* __restrict__ x,
                         const float* __restrict__ W,
                         float* __restrict__ out) {
    extern __shared__ float sm[];
    float* pri   = sm + SM_PRI;
    float* logit = sm + SM_LOG;
    float* prb   = sm + SM_PRB;
    float* red   = sm + SM_RED;
    float* outv  = sm + SM_OUTV;
    float* redw  = sm + SM_REDW;
    float* mxse  = sm + SM_MXSE;

    const int tid  = threadIdx.x;
    const int lane = tid & 31;
    const int wid  = tid >> 5;
    const int c    = blockIdx.x;        // capsule 0..9
    const int b0   = blockIdx.y * BT;   // batch base

    // =========== Phase 1: priors GEMM into SMEM + iter-0 mean accumulation ===========
    // 4 threads per routing node n; thread handles 4 contiguous DOUT (oq*4..oq*4+3).
    const int oq = tid & 3;
    const int g  = tid >> 2;            // 64 node-groups

    float s0[BT][4];
#pragma unroll
    for (int bt = 0; bt < BT; ++bt)
#pragma unroll
        for (int j = 0; j < 4; ++j) s0[bt][j] = 0.0f;

    for (int n = g; n < NN; n += 64) {
        const float4* Wr = reinterpret_cast<const float4*>(W + ((c * NN + n) * DIN) * DOUT);
        float xa[BT][8];
#pragma unroll
        for (int bt = 0; bt < BT; ++bt) {
            const float4* xr = reinterpret_cast<const float4*>(x + ((b0 + bt) * NN + n) * DIN);
            float4 v0 = xr[0], v1 = xr[1];
            xa[bt][0]=v0.x; xa[bt][1]=v0.y; xa[bt][2]=v0.z; xa[bt][3]=v0.w;
            xa[bt][4]=v1.x; xa[bt][5]=v1.y; xa[bt][6]=v1.z; xa[bt][7]=v1.w;
        }
        float acc[BT][4];
#pragma unroll
        for (int bt = 0; bt < BT; ++bt)
#pragma unroll
            for (int j = 0; j < 4; ++j) acc[bt][j] = 0.0f;

#pragma unroll
        for (int i = 0; i < 8; ++i) {
            float4 w = Wr[i * 4 + oq];
#pragma unroll
            for (int bt = 0; bt < BT; ++bt) {
                float xs = xa[bt][i];
                acc[bt][0] = fmaf(xs, w.x, acc[bt][0]);
                acc[bt][1] = fmaf(xs, w.y, acc[bt][1]);
                acc[bt][2] = fmaf(xs, w.z, acc[bt][2]);
                acc[bt][3] = fmaf(xs, w.w, acc[bt][3]);
            }
        }
#pragma unroll
        for (int bt = 0; bt < BT; ++bt) {
            float* p = pri + bt * (NN * NPAD) + n * NPAD + oq * 4;
#pragma unroll
            for (int j = 0; j < 4; ++j) {
                p[j] = acc[bt][j];
                s0[bt][j] += acc[bt][j];
            }
        }
    }

    // Reduce s0 across the 8 node-groups inside each warp (lanes with equal lane&3)
    for (int m = 4; m < 32; m <<= 1) {
#pragma unroll
        for (int bt = 0; bt < BT; ++bt)
#pragma unroll
            for (int j = 0; j < 4; ++j)
                s0[bt][j] += __shfl_xor_sync(0xffffffffu, s0[bt][j], m);
    }
    if (lane < 4) {
#pragma unroll
        for (int bt = 0; bt < BT; ++bt)
#pragma unroll
            for (int j = 0; j < 4; ++j)
                red[(bt * 16 + (lane * 4 + j)) * 8 + wid] = s0[bt][j];
    }
    __syncthreads();

    // Finalize iter-0: s = mean over n, squash -> outv
    if (tid < BT * 16) {
        const int bt = tid >> 4, o = tid & 15;
        float s = 0.0f;
#pragma unroll
        for (int w = 0; w < 8; ++w) s += red[(bt * 16 + o) * 8 + w];
        s *= (1.0f / (float)NN);
        float q = s * s;
        for (int m = 1; m < 16; m <<= 1) q += __shfl_xor_sync(0xffffffffu, q, m);
        float scale = q / ((1.0f + q) * sqrtf(q));
        outv[bt * 16 + o] = scale * s;
    }

    // =========== Phase 2: routing iterations 1 and 2 ===========
    for (int it = 0; it < 2; ++it) {
        __syncthreads();

        // Agreement update: logits[n] (+)= sum_o priors[n,o]*out[o]
        for (int n = tid; n < NN; n += THREADS) {
#pragma unroll
            for (int bt = 0; bt < BT; ++bt) {
                const float* p  = pri + bt * (NN * NPAD) + n * NPAD;
                const float* ov = outv + bt * 16;
                float d = 0.0f;
#pragma unroll
                for (int o = 0; o < DOUT; ++o) d = fmaf(p[o], ov[o], d);
                if (it == 0) logit[bt * NN + n] = d;
                else         logit[bt * NN + n] += d;
            }
        }
        __syncthreads();

        // Softmax over n, per bt: (a) max
        float mx[BT];
#pragma unroll
        for (int bt = 0; bt < BT; ++bt) mx[bt] = -1e30f;
        for (int n = tid; n < NN; n += THREADS) {
#pragma unroll
            for (int bt = 0; bt < BT; ++bt)
                mx[bt] = fmaxf(mx[bt], logit[bt * NN + n]);
        }
        for (int m = 1; m < 32; m <<= 1) {
#pragma unroll
            for (int bt = 0; bt < BT; ++bt)
                mx[bt] = fmaxf(mx[bt], __shfl_xor_sync(0xffffffffu, mx[bt], m));
        }
        if (lane == 0) { redw[wid] = mx[0]; redw[8 + wid] = mx[1]; }
        __syncthreads();
        if (tid == 0) {
            float a = -1e30f, b = -1e30f;
            for (int w = 0; w < 8; ++w) { a = fmaxf(a, redw[w]); b = fmaxf(b, redw[8 + w]); }
            mxse[0] = a; mxse[1] = b;
        }
        __syncthreads();

        // (b) exp + sum  (normalization folded into s later)
        float se[BT] = {0.0f, 0.0f};
        for (int n = tid; n < NN; n += THREADS) {
#pragma unroll
            for (int bt = 0; bt < BT; ++bt) {
                float e = __expf(logit[bt * NN + n] - mxse[bt]);
                prb[bt * NN + n] = e;
                se[bt] += e;
            }
        }
        for (int m = 1; m < 32; m <<= 1) {
#pragma unroll
            for (int bt = 0; bt < BT; ++bt)
                se[bt] += __shfl_xor_sync(0xffffffffu, se[bt], m);
        }
        if (lane == 0) { redw[wid] = se[0]; redw[8 + wid] = se[1]; }
        __syncthreads();
        if (tid == 0) {
            float a = 0.0f, b = 0.0f;
            for (int w = 0; w < 8; ++w) { a += redw[w]; b += redw[8 + w]; }
            mxse[2] = 1.0f / a; mxse[3] = 1.0f / b;
        }
        __syncthreads();

        // Weighted sum: s[o] = inv_se * sum_n e[n]*priors[n,o]
        const int o = tid & 15;
        const int r = tid >> 4;           // 16 node-stripes
        float sl[BT] = {0.0f, 0.0f};
        for (int n = r; n < NN; n += 16) {
#pragma unroll
            for (int bt = 0; bt < BT; ++bt)
                sl[bt] = fmaf(prb[bt * NN + n],
                              pri[bt * (NN * NPAD) + n * NPAD + o], sl[bt]);
        }
#pragma unroll
        for (int bt = 0; bt < BT; ++bt)
            sl[bt] += __shfl_xor_sync(0xffffffffu, sl[bt], 16);
        if (lane < 16) {
#pragma unroll
            for (int bt = 0; bt < BT; ++bt)
                red[(bt * 16 + o) * 8 + wid] = sl[bt];
        }
        __syncthreads();

        // Finalize: scale, squash, (last iter) write out
        if (tid < BT * 16) {
            const int bt = tid >> 4, oo = tid & 15;
            float s = 0.0f;
#pragma unroll
            for (int w = 0; w < 8; ++w) s += red[(bt * 16 + oo) * 8 + w];
            s *= mxse[2 + bt];
            float q = s * s;
            for (int m = 1; m < 16; m <<= 1) q += __shfl_xor_sync(0xffffffffu, q, m);
            float scale = q / ((1.0f + q) * sqrtf(q));
            float o_ = scale * s;
            outv[bt * 16 + oo] = o_;
            if (it == 1)
                out[((size_t)c * BB + (b0 + bt)) * DOUT + oo] = o_;
        }
    }
}

extern "C" void kernel_launch(void* const* d_in, const int* in_sizes, int n_in,
                              void* d_out, int out_size) {
    const float* x = (const float*)d_in[0];   // [256,1152,8]
    const float* W = (const float*)d_in[1];   // [10,1152,8,16]
    float* out = (float*)d_out;               // [10,256,1,16]

    static bool attr_set = false;
    const int smem_bytes = SM_FLOATS * (int)sizeof(float);
    // Idempotent, deterministic; needed for >48KB dynamic smem.
    cudaFuncSetAttribute(caps_routing_kernel,
                         cudaFuncAttributeMaxDynamicSharedMemorySize, smem_bytes);
    (void)attr_set;

    dim3 grid(CC, BB / BT);
    caps_routing_kernel<<<grid, THREADS, smem_bytes>>>(x, W, out);
}

// round 2
// speedup vs baseline: 1.0409x; 1.0409x over previous
#include <cuda_runtime.h>
#include <math.h>

#define CC    10
#define NN    1152
#define DIN   8
#define DOUT  16
#define BB    256
#define BT    2        // batch elements per CTA
#define NPAD  20       // priors row stride (16B-aligned, phase-conflict-free)
#define THREADS 512
#define NWARPS (THREADS/32)

// Shared memory layout (floats):
//   pri   : [BT][NN*NPAD]   = 46080
//   logit : [BT][NN]        =  2304
//   prb   : [BT][NN]        =  2304
//   red   : [BT][16][16]    =   512
//   outv  : [BT][16]        =    32
//   redw  : [2*16]          =    32
//   mxse  : [4]             =     4
#define SM_PRI   0
#define SM_LOG   (BT*NN*NPAD)
#define SM_PRB   (SM_LOG + BT*NN)
#define SM_RED   (SM_PRB + BT*NN)
#define SM_OUTV  (SM_RED + BT*16*NWARPS)
#define SM_REDW  (SM_OUTV + BT*16)
#define SM_MXSE  (SM_REDW + 2*NWARPS)
#define SM_FLOATS (SM_MXSE + 4)

__global__ __launch_bounds__(THREADS, 1)
void caps_routing_kernel(const float* __restrict__ x,
                         const float* __restrict__ W,
                         float* __restrict__ out) {
    extern __shared__ float sm[];
    float* pri   = sm + SM_PRI;
    float* logit = sm + SM_LOG;
    float* prb   = sm + SM_PRB;
    float* red   = sm + SM_RED;
    float* outv  = sm + SM_OUTV;
    float* redw  = sm + SM_REDW;
    float* mxse  = sm + SM_MXSE;

    const int tid  = threadIdx.x;
    const int lane = tid & 31;
    const int wid  = tid >> 5;
    const int c    = blockIdx.x;        // capsule 0..9
    const int b0   = blockIdx.y * BT;   // batch base

    // =========== Phase 1: priors GEMM into SMEM + iter-0 mean accumulation ===========
    // 4 threads per routing node n; thread handles 4 contiguous DOUT (oq*4..oq*4+3).
    const int oq = tid & 3;
    const int g  = tid >> 2;            // 128 node-groups -> 9 nodes each

    float s0[BT][4];
#pragma unroll
    for (int bt = 0; bt < BT; ++bt)
#pragma unroll
        for (int j = 0; j < 4; ++j) s0[bt][j] = 0.0f;

    for (int n = g; n < NN; n += 128) {
        const float4* Wr = reinterpret_cast<const float4*>(W + ((c * NN + n) * DIN) * DOUT);
        float xa[BT][8];
#pragma unroll
        for (int bt = 0; bt < BT; ++bt) {
            const float4* xr = reinterpret_cast<const float4*>(x + ((b0 + bt) * NN + n) * DIN);
            float4 v0 = xr[0], v1 = xr[1];
            xa[bt][0]=v0.x; xa[bt][1]=v0.y; xa[bt][2]=v0.z; xa[bt][3]=v0.w;
            xa[bt][4]=v1.x; xa[bt][5]=v1.y; xa[bt][6]=v1.z; xa[bt][7]=v1.w;
        }
        float acc[BT][4];
#pragma unroll
        for (int bt = 0; bt < BT; ++bt)
#pragma unroll
            for (int j = 0; j < 4; ++j) acc[bt][j] = 0.0f;

#pragma unroll
        for (int i = 0; i < 8; ++i) {
            float4 w = Wr[i * 4 + oq];
#pragma unroll
            for (int bt = 0; bt < BT; ++bt) {
                float xs = xa[bt][i];
                acc[bt][0] = fmaf(xs, w.x, acc[bt][0]);
                acc[bt][1] = fmaf(xs, w.y, acc[bt][1]);
                acc[bt][2] = fmaf(xs, w.z, acc[bt][2]);
                acc[bt][3] = fmaf(xs, w.w, acc[bt][3]);
            }
        }
#pragma unroll
        for (int bt = 0; bt < BT; ++bt) {
            float* p = pri + bt * (NN * NPAD) + n * NPAD + oq * 4;
            *reinterpret_cast<float4*>(p) =
                make_float4(acc[bt][0], acc[bt][1], acc[bt][2], acc[bt][3]);
#pragma unroll
            for (int j = 0; j < 4; ++j) s0[bt][j] += acc[bt][j];
        }
    }

    // Reduce s0 across the 8 node-groups inside each warp (lanes with equal lane&3)
    for (int m = 4; m < 32; m <<= 1) {
#pragma unroll
        for (int bt = 0; bt < BT; ++bt)
#pragma unroll
            for (int j = 0; j < 4; ++j)
                s0[bt][j] += __shfl_xor_sync(0xffffffffu, s0[bt][j], m);
    }
    if (lane < 4) {
#pragma unroll
        for (int bt = 0; bt < BT; ++bt)
#pragma unroll
            for (int j = 0; j < 4; ++j)
                red[(bt * 16 + (lane * 4 + j)) * NWARPS + wid] = s0[bt][j];
    }
    __syncthreads();

    // Finalize iter-0: s = mean over n, squash -> outv
    if (tid < BT * 16) {
        const int bt = tid >> 4, o = tid & 15;
        float s = 0.0f;
#pragma unroll
        for (int w = 0; w < NWARPS; ++w) s += red[(bt * 16 + o) * NWARPS + w];
        s *= (1.0f / (float)NN);
        float q = s * s;
        for (int m = 1; m < 16; m <<= 1) q += __shfl_xor_sync(0xffffffffu, q, m);
        float scale = q / ((1.0f + q) * sqrtf(q));
        outv[bt * 16 + o] = scale * s;
    }

    // =========== Phase 2: routing iterations 1 and 2 ===========
    for (int it = 0; it < 2; ++it) {
        __syncthreads();

        // Load current out vectors into registers (broadcast reads)
        float4 ovv[BT][4];
#pragma unroll
        for (int bt = 0; bt < BT; ++bt)
#pragma unroll
            for (int j = 0; j < 4; ++j)
                ovv[bt][j] = reinterpret_cast<float4*>(outv + bt * 16)[j];

        // Agreement update fused with running max:
        // logits[n] (+)= sum_o priors[n,o]*out[o]; track max(logit)
        float mx[BT];
#pragma unroll
        for (int bt = 0; bt < BT; ++bt) mx[bt] = -1e30f;

        for (int n = tid; n < NN; n += THREADS) {
#pragma unroll
            for (int bt = 0; bt < BT; ++bt) {
                const float4* p =
                    reinterpret_cast<const float4*>(pri + bt * (NN * NPAD) + n * NPAD);
                float d = 0.0f;
#pragma unroll
                for (int j = 0; j < 4; ++j) {
                    float4 pv = p[j];
                    d = fmaf(pv.x, ovv[bt][j].x, d);
                    d = fmaf(pv.y, ovv[bt][j].y, d);
                    d = fmaf(pv.z, ovv[bt][j].z, d);
                    d = fmaf(pv.w, ovv[bt][j].w, d);
                }
                float l = (it == 0) ? d : (logit[bt * NN + n] + d);
                logit[bt * NN + n] = l;
                mx[bt] = fmaxf(mx[bt], l);
            }
        }
        for (int m = 1; m < 32; m <<= 1) {
#pragma unroll
            for (int bt = 0; bt < BT; ++bt)
                mx[bt] = fmaxf(mx[bt], __shfl_xor_sync(0xffffffffu, mx[bt], m));
        }
        if (lane == 0) { redw[wid] = mx[0]; redw[NWARPS + wid] = mx[1]; }
        __syncthreads();
        if (tid == 0) {
            float a = -1e30f, b = -1e30f;
            for (int w = 0; w < NWARPS; ++w) {
                a = fmaxf(a, redw[w]); b = fmaxf(b, redw[NWARPS + w]);
            }
            mxse[0] = a; mxse[1] = b;
        }
        __syncthreads();

        // exp + sum (normalization folded into s later)
        float se[BT] = {0.0f, 0.0f};
        for (int n = tid; n < NN; n += THREADS) {
#pragma unroll
            for (int bt = 0; bt < BT; ++bt) {
                float e = __expf(logit[bt * NN + n] - mxse[bt]);
                prb[bt * NN + n] = e;
                se[bt] += e;
            }
        }
        for (int m = 1; m < 32; m <<= 1) {
#pragma unroll
            for (int bt = 0; bt < BT; ++bt)
                se[bt] += __shfl_xor_sync(0xffffffffu, se[bt], m);
        }
        if (lane == 0) { redw[wid] = se[0]; redw[NWARPS + wid] = se[1]; }
        __syncthreads();
        if (tid == 0) {
            float a = 0.0f, b = 0.0f;
            for (int w = 0; w < NWARPS; ++w) { a += redw[w]; b += redw[NWARPS + w]; }
            mxse[2] = 1.0f / a; mxse[3] = 1.0f / b;
        }
        __syncthreads();

        // Weighted sum: s[o] = inv_se * sum_n e[n]*priors[n,o]
        const int o = tid & 15;
        const int r = tid >> 4;           // 32 node-stripes
        float sl[BT] = {0.0f, 0.0f};
        for (int n = r; n < NN; n += 32) {
#pragma unroll
            for (int bt = 0; bt < BT; ++bt)
                sl[bt] = fmaf(prb[bt * NN + n],
                              pri[bt * (NN * NPAD) + n * NPAD + o], sl[bt]);
        }
#pragma unroll
        for (int bt = 0; bt < BT; ++bt)
            sl[bt] += __shfl_xor_sync(0xffffffffu, sl[bt], 16);
        if (lane < 16) {
#pragma unroll
            for (int bt = 0; bt < BT; ++bt)
                red[(bt * 16 + o) * NWARPS + wid] = sl[bt];
        }
        __syncthreads();

        // Finalize: scale, squash, (last iter) write out
        if (tid < BT * 16) {
            const int bt = tid >> 4, oo = tid & 15;
            float s = 0.0f;
#pragma unroll
            for (int w = 0; w < NWARPS; ++w) s += red[(bt * 16 + oo) * NWARPS + w];
            s *= mxse[2 + bt];
            float q = s * s;
            for (int m = 1; m < 16; m <<= 1) q += __shfl_xor_sync(0xffffffffu, q, m);
            float scale = q / ((1.0f + q) * sqrtf(q));
            float o_ = scale * s;
            outv[bt * 16 + oo] = o_;
            if (it == 1)
                out[((size_t)c * BB + (b0 + bt)) * DOUT + oo] = o_;
        }
    }
}

extern "C" void kernel_launch(void* const* d_in, const int* in_sizes, int n_in,
                              void* d_out, int out_size) {
    const float* x = (const float*)d_in[0];   // [256,1152,8]
    const float* W = (const float*)d_in[1];   // [10,1152,8,16]
    float* out = (float*)d_out;               // [10,256,1,16]

    const int smem_bytes = SM_FLOATS * (int)sizeof(float);
    // Idempotent, deterministic; needed for >48KB dynamic smem.
    cudaFuncSetAttribute(caps_routing_kernel,
                         cudaFuncAttributeMaxDynamicSharedMemorySize, smem_bytes);

    dim3 grid(CC, BB / BT);
    caps_routing_kernel<<<grid, THREADS, smem_bytes>>>(x, W, out);
}

// round 3
// speedup vs baseline: 1.6933x; 1.6268x over previous
#include <cuda_runtime.h>
#include <math.h>

#define CC    10
#define NN    1152
#define DIN   8
#define DOUT  16
#define BB    256
#define BT    2
#define THREADS 512
#define NWARPS  16
#define KPT     9      // nodes per thread: NN / (THREADS/4) = 1152/128

// Transposed weights: [c][i][n][o]  (5.9 MB scratch, written each launch)
__device__ float g_Wt[CC * DIN * NN * DOUT];

// ---------------- W transpose: [c][n][i][o] -> [c][i][n][o] ----------------
// One block per (c, 32-node tile). Reads 16KB contiguous, writes 8 contiguous
// 2KB chunks. Fully coalesced both directions via smem staging.
__global__ void transpose_W_kernel(const float4* __restrict__ W4) {
    __shared__ float4 tile[1024];              // 16 KB
    float4* Wt4 = reinterpret_cast<float4*>(g_Wt);
    const int c  = blockIdx.x / (NN / 32);
    const int n0 = (blockIdx.x % (NN / 32)) * 32;
    const int tid = threadIdx.x;               // 256

    const int in_base = (c * NN + n0) * 32;    // 32 float4 per node row
#pragma unroll
    for (int k = 0; k < 4; ++k)
        tile[tid + k * 256] = W4[in_base + tid + k * 256];
    __syncthreads();
#pragma unroll
    for (int k = 0; k < 4; ++k) {
        int j  = tid + k * 256;                // 0..1023 over output order
        int i  = j >> 7;                       // 0..7
        int nn = (j >> 2) & 31;                // 0..31
        int q  = j & 3;                        // float4 quad within o-dim
        Wt4[((c * DIN + i) * NN + n0 + nn) * 4 + q] = tile[nn * 32 + i * 4 + q];
    }
}

// ---------------- fused priors + routing, priors in registers ----------------
__global__ __launch_bounds__(THREADS, 1)
void caps_routing_kernel(const float* __restrict__ x,
                         float* __restrict__ out) {
    __shared__ float  red[BT * 16 * NWARPS];   // per-warp o-partials
    __shared__ float  redw_mx[BT * NWARPS];
    __shared__ float  redw_se[BT * NWARPS];
    __shared__ float4 outv4[BT * 4];           // out vectors, 16B aligned

    const int tid  = threadIdx.x;
    const int lane = tid & 31;
    const int wid  = tid >> 5;
    const int oq   = tid & 3;                  // o-quad: owns o = oq*4 .. oq*4+3
    const int g    = tid >> 2;                 // node group 0..127
    const int c    = blockIdx.x;
    const int b0   = blockIdx.y * BT;

    const float4* Wt4 = reinterpret_cast<const float4*>(g_Wt);
    float* outv = reinterpret_cast<float*>(outv4);

    // ===== Phase 1: priors into registers + iter-0 sum =====
    float pri[BT][KPT][4];
    float s0[BT][4];
#pragma unroll
    for (int bt = 0; bt < BT; ++bt)
#pragma unroll
        for (int j = 0; j < 4; ++j) s0[bt][j] = 0.0f;

#pragma unroll
    for (int k = 0; k < KPT; ++k) {
        const int n = g + 128 * k;
        float xa[BT][8];
#pragma unroll
        for (int bt = 0; bt < BT; ++bt) {
            const float4* xr = reinterpret_cast<const float4*>(x + ((b0 + bt) * NN + n) * DIN);
            float4 v0 = xr[0], v1 = xr[1];
            xa[bt][0]=v0.x; xa[bt][1]=v0.y; xa[bt][2]=v0.z; xa[bt][3]=v0.w;
            xa[bt][4]=v1.x; xa[bt][5]=v1.y; xa[bt][6]=v1.z; xa[bt][7]=v1.w;
        }
        float acc[BT][4];
#pragma unroll
        for (int bt = 0; bt < BT; ++bt)
#pragma unroll
            for (int j = 0; j < 4; ++j) acc[bt][j] = 0.0f;
#pragma unroll
        for (int i = 0; i < 8; ++i) {
            // warp reads 512B contiguous: lanes = (8 consecutive n) x (4 o-quads)
            float4 w = Wt4[((c * DIN + i) * NN + n) * 4 + oq];
#pragma unroll
            for (int bt = 0; bt < BT; ++bt) {
                float xs = xa[bt][i];
                acc[bt][0] = fmaf(xs, w.x, acc[bt][0]);
                acc[bt][1] = fmaf(xs, w.y, acc[bt][1]);
                acc[bt][2] = fmaf(xs, w.z, acc[bt][2]);
                acc[bt][3] = fmaf(xs, w.w, acc[bt][3]);
            }
        }
#pragma unroll
        for (int bt = 0; bt < BT; ++bt)
#pragma unroll
            for (int j = 0; j < 4; ++j) {
                pri[bt][k][j] = acc[bt][j];
                s0[bt][j] += acc[bt][j];
            }
    }

    // reduce s0 over the 8 node-groups in each warp (lanes sharing oq)
    for (int m = 4; m < 32; m <<= 1)
#pragma unroll
        for (int bt = 0; bt < BT; ++bt)
#pragma unroll
            for (int j = 0; j < 4; ++j)
                s0[bt][j] += __shfl_xor_sync(0xffffffffu, s0[bt][j], m);
    if (lane < 4)
#pragma unroll
        for (int bt = 0; bt < BT; ++bt)
#pragma unroll
            for (int j = 0; j < 4; ++j)
                red[(bt * 16 + (lane * 4 + j)) * NWARPS + wid] = s0[bt][j];
    __syncthreads();

    // iter-0 finalize: s = mean over n, squash
    if (tid < BT * 16) {
        const int bt = tid >> 4, o = tid & 15;
        float s = 0.0f;
#pragma unroll
        for (int w = 0; w < NWARPS; ++w) s += red[(bt * 16 + o) * NWARPS + w];
        s *= (1.0f / (float)NN);
        float q = s * s;
        for (int m = 1; m < 16; m <<= 1) q += __shfl_xor_sync(0xffffffffu, q, m);
        float scale = q / ((1.0f + q) * sqrtf(q));
        outv[bt * 16 + o] = scale * s;
    }

    // ===== Routing iterations 1..2 (logits persistent in registers) =====
    float lg[BT][KPT];
#pragma unroll
    for (int bt = 0; bt < BT; ++bt)
#pragma unroll
        for (int k = 0; k < KPT; ++k) lg[bt][k] = 0.0f;

    for (int it = 0; it < 2; ++it) {
        __syncthreads();

        float4 ovq[BT];
#pragma unroll
        for (int bt = 0; bt < BT; ++bt) ovq[bt] = outv4[bt * 4 + oq];

        // agreement: lg[n] += priors[n,:] . out ; track max
        float mxb[BT];
#pragma unroll
        for (int bt = 0; bt < BT; ++bt) mxb[bt] = -1e30f;
#pragma unroll
        for (int k = 0; k < KPT; ++k) {
#pragma unroll
            for (int bt = 0; bt < BT; ++bt) {
                float d = pri[bt][k][0] * ovq[bt].x;
                d = fmaf(pri[bt][k][1], ovq[bt].y, d);
                d = fmaf(pri[bt][k][2], ovq[bt].z, d);
                d = fmaf(pri[bt][k][3], ovq[bt].w, d);
                d += __shfl_xor_sync(0xffffffffu, d, 1);
                d += __shfl_xor_sync(0xffffffffu, d, 2);
                lg[bt][k] += d;
                mxb[bt] = fmaxf(mxb[bt], lg[bt][k]);
            }
        }
        for (int m = 1; m < 32; m <<= 1)
#pragma unroll
            for (int bt = 0; bt < BT; ++bt)
                mxb[bt] = fmaxf(mxb[bt], __shfl_xor_sync(0xffffffffu, mxb[bt], m));
        if (lane == 0) {
            redw_mx[wid]          = mxb[0];
            redw_mx[NWARPS + wid] = mxb[1];
        }
        __syncthreads();
#pragma unroll
        for (int bt = 0; bt < BT; ++bt) {
            float m = -1e30f;
#pragma unroll
            for (int w = 0; w < NWARPS; ++w)
                m = fmaxf(m, redw_mx[bt * NWARPS + w]);
            mxb[bt] = m;
        }

        // exp + fused weighted-sum with UNNORMALIZED weights
        float sp[BT][4];
        float se[BT];
#pragma unroll
        for (int bt = 0; bt < BT; ++bt) {
            se[bt] = 0.0f;
#pragma unroll
            for (int j = 0; j < 4; ++j) sp[bt][j] = 0.0f;
        }
#pragma unroll
        for (int k = 0; k < KPT; ++k)
#pragma unroll
            for (int bt = 0; bt < BT; ++bt) {
                float e = __expf(lg[bt][k] - mxb[bt]);
                se[bt] += e;
#pragma unroll
                for (int j = 0; j < 4; ++j)
                    sp[bt][j] = fmaf(e, pri[bt][k][j], sp[bt][j]);
            }
        // se: full-warp reduce (4x redundancy across oq -> exactly 4*true)
        for (int m = 1; m < 32; m <<= 1)
#pragma unroll
            for (int bt = 0; bt < BT; ++bt)
                se[bt] += __shfl_xor_sync(0xffffffffu, se[bt], m);
        // sp: reduce across node-groups only (keep oq distinct)
        for (int m = 4; m < 32; m <<= 1)
#pragma unroll
            for (int bt = 0; bt < BT; ++bt)
#pragma unroll
                for (int j = 0; j < 4; ++j)
                    sp[bt][j] += __shfl_xor_sync(0xffffffffu, sp[bt][j], m);
        if (lane == 0) {
            redw_se[wid]          = se[0];
            redw_se[NWARPS + wid] = se[1];
        }
        if (lane < 4)
#pragma unroll
            for (int bt = 0; bt < BT; ++bt)
#pragma unroll
                for (int j = 0; j < 4; ++j)
                    red[(bt * 16 + (lane * 4 + j)) * NWARPS + wid] = sp[bt][j];
        __syncthreads();

        // finalize: normalize, squash, write
        if (tid < BT * 16) {
            const int bt = tid >> 4, o = tid & 15;
            float sps = 0.0f, ses = 0.0f;
#pragma unroll
            for (int w = 0; w < NWARPS; ++w) {
                sps += red[(bt * 16 + o) * NWARPS + w];
                ses += redw_se[bt * NWARPS + w];
            }
            float s = sps * (4.0f / ses);     // /4 undoes oq redundancy exactly
            float q = s * s;
            for (int m = 1; m < 16; m <<= 1) q += __shfl_xor_sync(0xffffffffu, q, m);
            float scale = q / ((1.0f + q) * sqrtf(q));
            float o_ = scale * s;
            outv[bt * 16 + o] = o_;
            if (it == 1)
                out[((size_t)c * BB + (b0 + bt)) * DOUT + o] = o_;
        }
    }
}

extern "C" void kernel_launch(void* const* d_in, const int* in_sizes, int n_in,
                              void* d_out, int out_size) {
    const float* x = (const float*)d_in[0];   // [256,1152,8]
    const float* W = (const float*)d_in[1];   // [10,1152,8,16]
    float* out = (float*)d_out;               // [10,256,1,16]

    transpose_W_kernel<<<CC * (NN / 32), 256>>>(reinterpret_cast<const float4*>(W));

    dim3 grid(CC, BB / BT);
    caps_routing_kernel<<<grid, THREADS>>>(x, out);
}

// round 4
// speedup vs baseline: 1.8083x; 1.0679x over previous
#include <cuda_runtime.h>
#include <math.h>

#define CC    10
#define NN    1152
#define DIN   8
#define DOUT  16
#define BB    256
#define BT    2
#define THREADS 512
#define NWARPS  16
#define KPT     9      // nodes per thread: NN / (THREADS/4)

typedef unsigned long long ull;

// Transposed weights: [c][i][n][o]  (5.9 MB scratch, written each launch)
__device__ float g_Wt[CC * DIN * NN * DOUT];

// ---- packed f32x2 helpers (Blackwell FFMA2 — PTX-only, ptxas won't auto-fuse) ----
__device__ __forceinline__ ull pack2(float lo, float hi) {
    ull r; asm("mov.b64 %0, {%1, %2};" : "=l"(r) : "f"(lo), "f"(hi)); return r;
}
__device__ __forceinline__ float2 unpack2(ull v) {
    float2 f; asm("mov.b64 {%0, %1}, %2;" : "=f"(f.x), "=f"(f.y) : "l"(v)); return f;
}
__device__ __forceinline__ ull fma2(ull a, ull b, ull c) {
    ull d; asm("fma.rn.f32x2 %0, %1, %2, %3;" : "=l"(d) : "l"(a), "l"(b), "l"(c)); return d;
}
__device__ __forceinline__ ull add2(ull a, ull b) {
    ull d; asm("add.rn.f32x2 %0, %1, %2;" : "=l"(d) : "l"(a), "l"(b)); return d;
}

// ---------------- W transpose: [c][n][i][o] -> [c][i][n][o] ----------------
__global__ void transpose_W_kernel(const float4* __restrict__ W4) {
    __shared__ float4 tile[1024];              // 16 KB
    float4* Wt4 = reinterpret_cast<float4*>(g_Wt);
    const int c  = blockIdx.x / (NN / 32);
    const int n0 = (blockIdx.x % (NN / 32)) * 32;
    const int tid = threadIdx.x;               // 256

    const int in_base = (c * NN + n0) * 32;    // 32 float4 per node row
#pragma unroll
    for (int k = 0; k < 4; ++k)
        tile[tid + k * 256] = W4[in_base + tid + k * 256];
    __syncthreads();
#pragma unroll
    for (int k = 0; k < 4; ++k) {
        int j  = tid + k * 256;                // 0..1023 over output order
        int i  = j >> 7;                       // 0..7
        int nn = (j >> 2) & 31;                // 0..31
        int q  = j & 3;                        // float4 quad within o-dim
        Wt4[((c * DIN + i) * NN + n0 + nn) * 4 + q] = tile[nn * 32 + i * 4 + q];
    }
}

// ---------------- fused priors + routing, priors packed f32x2 in regs ----------------
__global__ __launch_bounds__(THREADS, 1)
void caps_routing_kernel(const float* __restrict__ x,
                         float* __restrict__ out) {
    __shared__ float  red[BT * 16 * NWARPS];   // per-warp o-partials
    __shared__ float  redw_se[BT * NWARPS];    // per-warp exp-sum partials
    __shared__ float4 outv4[BT * 4];           // out vectors, 16B aligned

    const int tid  = threadIdx.x;
    const int lane = tid & 31;
    const int wid  = tid >> 5;
    const int oq   = tid & 3;                  // o-quad: owns o = oq*4 .. oq*4+3
    const int g    = tid >> 2;                 // node group 0..127
    const int c    = blockIdx.x;
    const int b0   = blockIdx.y * BT;

    const float4* Wt4 = reinterpret_cast<const float4*>(g_Wt);
    float* outv = reinterpret_cast<float*>(outv4);

    // ===== Phase 1: priors into registers (f32x2 o-pairs) + iter-0 sum =====
    ull pri2[BT][KPT][2];                      // lanes = (o, o+1)
    ull s02[BT][2] = {{0ull, 0ull}, {0ull, 0ull}};

#pragma unroll
    for (int k = 0; k < KPT; ++k) {
        const int n = g + 128 * k;
        float xa[BT][8];
#pragma unroll
        for (int bt = 0; bt < BT; ++bt) {
            const float4* xr = reinterpret_cast<const float4*>(x + ((b0 + bt) * NN + n) * DIN);
            float4 v0 = xr[0], v1 = xr[1];
            xa[bt][0]=v0.x; xa[bt][1]=v0.y; xa[bt][2]=v0.z; xa[bt][3]=v0.w;
            xa[bt][4]=v1.x; xa[bt][5]=v1.y; xa[bt][6]=v1.z; xa[bt][7]=v1.w;
        }
        ull acc2[BT][2] = {{0ull, 0ull}, {0ull, 0ull}};
#pragma unroll
        for (int i = 0; i < 8; ++i) {
            // warp reads 512B contiguous: lanes = (8 consecutive n) x (4 o-quads)
            float4 w = Wt4[((c * DIN + i) * NN + n) * 4 + oq];
            ull b01 = pack2(w.x, w.y);
            ull b23 = pack2(w.z, w.w);
#pragma unroll
            for (int bt = 0; bt < BT; ++bt) {
                ull xs = pack2(xa[bt][i], xa[bt][i]);
                acc2[bt][0] = fma2(xs, b01, acc2[bt][0]);
                acc2[bt][1] = fma2(xs, b23, acc2[bt][1]);
            }
        }
#pragma unroll
        for (int bt = 0; bt < BT; ++bt)
#pragma unroll
            for (int j2 = 0; j2 < 2; ++j2) {
                pri2[bt][k][j2] = acc2[bt][j2];
                s02[bt][j2] = add2(s02[bt][j2], acc2[bt][j2]);
            }
    }

    // unpack iter-0 partial sums, reduce over the 8 node-groups per warp
    float s0[BT][4];
#pragma unroll
    for (int bt = 0; bt < BT; ++bt) {
        float2 a = unpack2(s02[bt][0]), b = unpack2(s02[bt][1]);
        s0[bt][0] = a.x; s0[bt][1] = a.y; s0[bt][2] = b.x; s0[bt][3] = b.y;
    }
    for (int m = 4; m < 32; m <<= 1)
#pragma unroll
        for (int bt = 0; bt < BT; ++bt)
#pragma unroll
            for (int j = 0; j < 4; ++j)
                s0[bt][j] += __shfl_xor_sync(0xffffffffu, s0[bt][j], m);
    if (lane < 4)
#pragma unroll
        for (int bt = 0; bt < BT; ++bt)
#pragma unroll
            for (int j = 0; j < 4; ++j)
                red[(bt * 16 + (lane * 4 + j)) * NWARPS + wid] = s0[bt][j];
    __syncthreads();

    // iter-0 finalize: s = mean over n, squash
    if (tid < BT * 16) {
        const int bt = tid >> 4, o = tid & 15;
        float s = 0.0f;
#pragma unroll
        for (int w = 0; w < NWARPS; ++w) s += red[(bt * 16 + o) * NWARPS + w];
        s *= (1.0f / (float)NN);
        float q = s * s;
        for (int m = 1; m < 16; m <<= 1) q += __shfl_xor_sync(0xffffffffu, q, m);
        float scale = q / ((1.0f + q) * sqrtf(q));
        outv[bt * 16 + o] = scale * s;
    }

    // ===== Routing iterations 1..2 (logits persistent in registers) =====
    float lg[BT][KPT];
#pragma unroll
    for (int bt = 0; bt < BT; ++bt)
#pragma unroll
        for (int k = 0; k < KPT; ++k) lg[bt][k] = 0.0f;

    for (int it = 0; it < 2; ++it) {
        __syncthreads();

        // out vector o-pairs for this thread's quad (8B-aligned smem reads)
        ull ov2[BT][2];
#pragma unroll
        for (int bt = 0; bt < BT; ++bt) {
            const ull* ovp = reinterpret_cast<const ull*>(outv + bt * 16 + oq * 4);
            ov2[bt][0] = ovp[0];
            ov2[bt][1] = ovp[1];
        }

        // agreement: lg[n] += priors[n,:] . out   (no max pass — exp is safe:
        // |logit| <= sum_iter ||pri_row||*||out||, and squash keeps ||out||<1)
#pragma unroll
        for (int k = 0; k < KPT; ++k) {
#pragma unroll
            for (int bt = 0; bt < BT; ++bt) {
                ull d2 = fma2(pri2[bt][k][0], ov2[bt][0],
                              fma2(pri2[bt][k][1], ov2[bt][1], 0ull));
                float2 dd = unpack2(d2);
                float d = dd.x + dd.y;
                d += __shfl_xor_sync(0xffffffffu, d, 1);
                d += __shfl_xor_sync(0xffffffffu, d, 2);
                lg[bt][k] += d;
            }
        }

        // exp + fused weighted-sum with UNNORMALIZED weights
        ull sp2[BT][2] = {{0ull, 0ull}, {0ull, 0ull}};
        float se[BT] = {0.0f, 0.0f};
#pragma unroll
        for (int k = 0; k < KPT; ++k)
#pragma unroll
            for (int bt = 0; bt < BT; ++bt) {
                float e = __expf(lg[bt][k]);
                se[bt] += e;
                ull e2 = pack2(e, e);
                sp2[bt][0] = fma2(e2, pri2[bt][k][0], sp2[bt][0]);
                sp2[bt][1] = fma2(e2, pri2[bt][k][1], sp2[bt][1]);
            }
        float sp[BT][4];
#pragma unroll
        for (int bt = 0; bt < BT; ++bt) {
            float2 a = unpack2(sp2[bt][0]), b = unpack2(sp2[bt][1]);
            sp[bt][0] = a.x; sp[bt][1] = a.y; sp[bt][2] = b.x; sp[bt][3] = b.y;
        }
        // se: full-warp reduce (4x redundancy across oq -> exactly 4*true)
        for (int m = 1; m < 32; m <<= 1)
#pragma unroll
            for (int bt = 0; bt < BT; ++bt)
                se[bt] += __shfl_xor_sync(0xffffffffu, se[bt], m);
        // sp: reduce across node-groups only (keep oq distinct)
        for (int m = 4; m < 32; m <<= 1)
#pragma unroll
            for (int bt = 0; bt < BT; ++bt)
#pragma unroll
                for (int j = 0; j < 4; ++j)
                    sp[bt][j] += __shfl_xor_sync(0xffffffffu, sp[bt][j], m);
        if (lane == 0) {
            redw_se[wid]          = se[0];
            redw_se[NWARPS + wid] = se[1];
        }
        if (lane < 4)
#pragma unroll
            for (int bt = 0; bt < BT; ++bt)
#pragma unroll
                for (int j = 0; j < 4; ++j)
                    red[(bt * 16 + (lane * 4 + j)) * NWARPS + wid] = sp[bt][j];
        __syncthreads();

        // finalize: normalize, squash, write
        if (tid < BT * 16) {
            const int bt = tid >> 4, o = tid & 15;
            float sps = 0.0f, ses = 0.0f;
#pragma unroll
            for (int w = 0; w < NWARPS; ++w) {
                sps += red[(bt * 16 + o) * NWARPS + w];
                ses += redw_se[bt * NWARPS + w];
            }
            float s = sps * (4.0f / ses);     // /4 undoes oq redundancy exactly
            float q = s * s;
            for (int m = 1; m < 16; m <<= 1) q += __shfl_xor_sync(0xffffffffu, q, m);
            float scale = q / ((1.0f + q) * sqrtf(q));
            float o_ = scale * s;
            outv[bt * 16 + o] = o_;
            if (it == 1)
                out[((size_t)c * BB + (b0 + bt)) * DOUT + o] = o_;
        }
    }
}

extern "C" void kernel_launch(void* const* d_in, const int* in_sizes, int n_in,
                              void* d_out, int out_size) {
    const float* x = (const float*)d_in[0];   // [256,1152,8]
    const float* W = (const float*)d_in[1];   // [10,1152,8,16]
    float* out = (float*)d_out;               // [10,256,1,16]

    transpose_W_kernel<<<CC * (NN / 32), 256>>>(reinterpret_cast<const float4*>(W));

    dim3 grid(CC, BB / BT);
    caps_routing_kernel<<<grid, THREADS>>>(x, out);
}

// round 5
// speedup vs baseline: 1.9123x; 1.0575x over previous
#include <cuda_runtime.h>
#include <cuda_fp16.h>
#include <math.h>

#define CC    10
#define NN    1152
#define DIN   8
#define DOUT  16
#define BB    256
#define BT    2
#define THREADS 512
#define NWARPS  16
#define KPT     9      // nodes per thread: NN / (THREADS/4)

typedef unsigned long long ull;

// Transposed fp16 weights: [c][i][n][o]  (2.95 MB scratch, written each launch)
__device__ __half g_Wh[CC * DIN * NN * DOUT];

// ---- packed f32x2 helpers (Blackwell FFMA2 — PTX-only, ptxas won't auto-fuse) ----
__device__ __forceinline__ ull pack2(float lo, float hi) {
    ull r; asm("mov.b64 %0, {%1, %2};" : "=l"(r) : "f"(lo), "f"(hi)); return r;
}
__device__ __forceinline__ float2 unpack2(ull v) {
    float2 f; asm("mov.b64 {%0, %1}, %2;" : "=f"(f.x), "=f"(f.y) : "l"(v)); return f;
}
__device__ __forceinline__ ull fma2(ull a, ull b, ull c) {
    ull d; asm("fma.rn.f32x2 %0, %1, %2, %3;" : "=l"(d) : "l"(a), "l"(b), "l"(c)); return d;
}
__device__ __forceinline__ ull add2(ull a, ull b) {
    ull d; asm("add.rn.f32x2 %0, %1, %2;" : "=l"(d) : "l"(a), "l"(b)); return d;
}
// half2 (lo,hi) -> packed f32x2 (lo,hi)
__device__ __forceinline__ ull h2_to_f32x2(unsigned int h2) {
    ull d;
    asm("{\n\t"
        ".reg .f16 h0, h1;\n\t"
        ".reg .f32 f0, f1;\n\t"
        "mov.b32 {h0, h1}, %1;\n\t"
        "cvt.f32.f16 f0, h0;\n\t"
        "cvt.f32.f16 f1, h1;\n\t"
        "mov.b64 %0, {f0, f1};\n\t"
        "}" : "=l"(d) : "r"(h2));
    return d;
}

// ------- W transpose + fp16 convert: [c][n][i][o] f32 -> [c][i][n][o] f16 -------
__global__ void transpose_W_kernel(const float4* __restrict__ W4) {
    __shared__ float4 tile[1024];              // 16 KB
    uint2* Wh8 = reinterpret_cast<uint2*>(g_Wh);   // 8B = 4 halves
    const int c  = blockIdx.x / (NN / 32);
    const int n0 = (blockIdx.x % (NN / 32)) * 32;
    const int tid = threadIdx.x;               // 256

    const int in_base = (c * NN + n0) * 32;    // 32 float4 per node row
#pragma unroll
    for (int k = 0; k < 4; ++k)
        tile[tid + k * 256] = W4[in_base + tid + k * 256];
    __syncthreads();
#pragma unroll
    for (int k = 0; k < 4; ++k) {
        int j  = tid + k * 256;                // 0..1023 over output order
        int i  = j >> 7;                       // 0..7
        int nn = (j >> 2) & 31;                // 0..31
        int q  = j & 3;                        // 4-half quad within o-dim
        float4 v = tile[nn * 32 + i * 4 + q];
        __half2 a = __floats2half2_rn(v.x, v.y);   // lo = v.x
        __half2 b = __floats2half2_rn(v.z, v.w);
        uint2 o;
        o.x = *reinterpret_cast<unsigned int*>(&a);
        o.y = *reinterpret_cast<unsigned int*>(&b);
        Wh8[((c * DIN + i) * NN + n0 + nn) * 4 + q] = o;
    }
}

// ---------------- fused priors + routing, priors packed f32x2 in regs ----------------
__global__ __launch_bounds__(THREADS, 1)
void caps_routing_kernel(const float* __restrict__ x,
                         float* __restrict__ out) {
    __shared__ float  red[BT * 16 * NWARPS];   // per-warp o-partials
    __shared__ float  redw_se[BT * NWARPS];    // per-warp exp-sum partials
    __shared__ float4 outv4[BT * 4];           // out vectors, 16B aligned

    const int tid  = threadIdx.x;
    const int lane = tid & 31;
    const int wid  = tid >> 5;
    const int oq   = tid & 3;                  // o-quad: owns o = oq*4 .. oq*4+3
    const int g    = tid >> 2;                 // node group 0..127
    const int c    = blockIdx.x;
    const int b0   = blockIdx.y * BT;

    const uint2* Wh8 = reinterpret_cast<const uint2*>(g_Wh);
    float* outv = reinterpret_cast<float*>(outv4);

    // ===== Phase 1: priors into registers (f32x2 o-pairs) + iter-0 sum =====
    ull pri2[BT][KPT][2];                      // lanes = (o, o+1)
    ull s02[BT][2] = {{0ull, 0ull}, {0ull, 0ull}};

#pragma unroll
    for (int k = 0; k < KPT; ++k) {
        const int n = g + 128 * k;
        float xa[BT][8];
#pragma unroll
        for (int bt = 0; bt < BT; ++bt) {
            const float4* xr = reinterpret_cast<const float4*>(x + ((b0 + bt) * NN + n) * DIN);
            float4 v0 = xr[0], v1 = xr[1];
            xa[bt][0]=v0.x; xa[bt][1]=v0.y; xa[bt][2]=v0.z; xa[bt][3]=v0.w;
            xa[bt][4]=v1.x; xa[bt][5]=v1.y; xa[bt][6]=v1.z; xa[bt][7]=v1.w;
        }
        ull acc2[BT][2] = {{0ull, 0ull}, {0ull, 0ull}};
#pragma unroll
        for (int i = 0; i < 8; ++i) {
            // warp reads 256B contiguous fp16: lanes = (8 consecutive n) x (4 o-quads)
            uint2 w = Wh8[((c * DIN + i) * NN + n) * 4 + oq];
            ull b01 = h2_to_f32x2(w.x);
            ull b23 = h2_to_f32x2(w.y);
#pragma unroll
            for (int bt = 0; bt < BT; ++bt) {
                ull xs = pack2(xa[bt][i], xa[bt][i]);
                acc2[bt][0] = fma2(xs, b01, acc2[bt][0]);
                acc2[bt][1] = fma2(xs, b23, acc2[bt][1]);
            }
        }
#pragma unroll
        for (int bt = 0; bt < BT; ++bt)
#pragma unroll
            for (int j2 = 0; j2 < 2; ++j2) {
                pri2[bt][k][j2] = acc2[bt][j2];
                s02[bt][j2] = add2(s02[bt][j2], acc2[bt][j2]);
            }
    }

    // unpack iter-0 partial sums, reduce over the 8 node-groups per warp
    float s0[BT][4];
#pragma unroll
    for (int bt = 0; bt < BT; ++bt) {
        float2 a = unpack2(s02[bt][0]), b = unpack2(s02[bt][1]);
        s0[bt][0] = a.x; s0[bt][1] = a.y; s0[bt][2] = b.x; s0[bt][3] = b.y;
    }
    for (int m = 4; m < 32; m <<= 1)
#pragma unroll
        for (int bt = 0; bt < BT; ++bt)
#pragma unroll
            for (int j = 0; j < 4; ++j)
                s0[bt][j] += __shfl_xor_sync(0xffffffffu, s0[bt][j], m);
    if (lane < 4)
#pragma unroll
        for (int bt = 0; bt < BT; ++bt)
#pragma unroll
            for (int j = 0; j < 4; ++j)
                red[(bt * 16 + (lane * 4 + j)) * NWARPS + wid] = s0[bt][j];
    __syncthreads();

    // iter-0 finalize: s = mean over n, squash
    if (tid < BT * 16) {
        const int bt = tid >> 4, o = tid & 15;
        float s = 0.0f;
#pragma unroll
        for (int w = 0; w < NWARPS; ++w) s += red[(bt * 16 + o) * NWARPS + w];
        s *= (1.0f / (float)NN);
        float q = s * s;
        for (int m = 1; m < 16; m <<= 1) q += __shfl_xor_sync(0xffffffffu, q, m);
        float scale = q / ((1.0f + q) * sqrtf(q));
        outv[bt * 16 + o] = scale * s;
    }

    // ===== Routing iterations 1..2 (logits persistent in registers) =====
    float lg[BT][KPT];
#pragma unroll
    for (int bt = 0; bt < BT; ++bt)
#pragma unroll
        for (int k = 0; k < KPT; ++k) lg[bt][k] = 0.0f;

    for (int it = 0; it < 2; ++it) {
        __syncthreads();

        // out vector o-pairs for this thread's quad (8B-aligned smem reads)
        ull ov2[BT][2];
#pragma unroll
        for (int bt = 0; bt < BT; ++bt) {
            const ull* ovp = reinterpret_cast<const ull*>(outv + bt * 16 + oq * 4);
            ov2[bt][0] = ovp[0];
            ov2[bt][1] = ovp[1];
        }

        // agreement: lg[n] += priors[n,:] . out   (no max pass — exp is safe:
        // |logit| <= sum_iter ||pri_row||*||out||, and squash keeps ||out||<1)
#pragma unroll
        for (int k = 0; k < KPT; ++k) {
#pragma unroll
            for (int bt = 0; bt < BT; ++bt) {
                ull d2 = fma2(pri2[bt][k][0], ov2[bt][0],
                              fma2(pri2[bt][k][1], ov2[bt][1], 0ull));
                float2 dd = unpack2(d2);
                float d = dd.x + dd.y;
                d += __shfl_xor_sync(0xffffffffu, d, 1);
                d += __shfl_xor_sync(0xffffffffu, d, 2);
                lg[bt][k] += d;
            }
        }

        // exp + fused weighted-sum with UNNORMALIZED weights
        ull sp2[BT][2] = {{0ull, 0ull}, {0ull, 0ull}};
        float se[BT] = {0.0f, 0.0f};
#pragma unroll
        for (int k = 0; k < KPT; ++k)
#pragma unroll
            for (int bt = 0; bt < BT; ++bt) {
                float e = __expf(lg[bt][k]);
                se[bt] += e;
                ull e2 = pack2(e, e);
                sp2[bt][0] = fma2(e2, pri2[bt][k][0], sp2[bt][0]);
                sp2[bt][1] = fma2(e2, pri2[bt][k][1], sp2[bt][1]);
            }
        float sp[BT][4];
#pragma unroll
        for (int bt = 0; bt < BT; ++bt) {
            float2 a = unpack2(sp2[bt][0]), b = unpack2(sp2[bt][1]);
            sp[bt][0] = a.x; sp[bt][1] = a.y; sp[bt][2] = b.x; sp[bt][3] = b.y;
        }
        // se: full-warp reduce (4x redundancy across oq -> exactly 4*true)
        for (int m = 1; m < 32; m <<= 1)
#pragma unroll
            for (int bt = 0; bt < BT; ++bt)
                se[bt] += __shfl_xor_sync(0xffffffffu, se[bt], m);
        // sp: reduce across node-groups only (keep oq distinct)
        for (int m = 4; m < 32; m <<= 1)
#pragma unroll
            for (int bt = 0; bt < BT; ++bt)
#pragma unroll
                for (int j = 0; j < 4; ++j)
                    sp[bt][j] += __shfl_xor_sync(0xffffffffu, sp[bt][j], m);
        if (lane == 0) {
            redw_se[wid]          = se[0];
            redw_se[NWARPS + wid] = se[1];
        }
        if (lane < 4)
#pragma unroll
            for (int bt = 0; bt < BT; ++bt)
#pragma unroll
                for (int j = 0; j < 4; ++j)
                    red[(bt * 16 + (lane * 4 + j)) * NWARPS + wid] = sp[bt][j];
        __syncthreads();

        // finalize: normalize, squash, write
        if (tid < BT * 16) {
            const int bt = tid >> 4, o = tid & 15;
            float sps = 0.0f, ses = 0.0f;
#pragma unroll
            for (int w = 0; w < NWARPS; ++w) {
                sps += red[(bt * 16 + o) * NWARPS + w];
                ses += redw_se[bt * NWARPS + w];
            }
            float s = sps * (4.0f / ses);     // /4 undoes oq redundancy exactly
            float q = s * s;
            for (int m = 1; m < 16; m <<= 1) q += __shfl_xor_sync(0xffffffffu, q, m);
            float scale = q / ((1.0f + q) * sqrtf(q));
            float o_ = scale * s;
            outv[bt * 16 + o] = o_;
            if (it == 1)
                out[((size_t)c * BB + (b0 + bt)) * DOUT + o] = o_;
        }
    }
}

extern "C" void kernel_launch(void* const* d_in, const int* in_sizes, int n_in,
                              void* d_out, int out_size) {
    const float* x = (const float*)d_in[0];   // [256,1152,8]
    const float* W = (const float*)d_in[1];   // [10,1152,8,16]
    float* out = (float*)d_out;               // [10,256,1,16]

    transpose_W_kernel<<<CC * (NN / 32), 256>>>(reinterpret_cast<const float4*>(W));

    dim3 grid(CC, BB / BT);
    caps_routing_kernel<<<grid, THREADS>>>(x, out);
}